// round 9
// baseline (speedup 1.0000x reference)
#include <cuda_runtime.h>
#include <math.h>

#define NN 100000
#define DD 128
#define HH 16
#define EE 1600000
#define BB 16384
#define FULL 0xffffffffu

#define PROJ_BLOCKS ((NN + 127) / 128)      // 782
#define DEG_BLOCKS  ((EE / 4 + 255) / 256)  // 1563
#define SCAN_BLOCKS 98

typedef unsigned long long u64;

// ---------------- scratch (device globals) ---------------------------------
__device__ int    g_degi[NN];
__device__ int    g_bsum[SCAN_BLOCKS];
__device__ int    g_boff[SCAN_BLOCKS];
__device__ int    g_row [NN];       // exclusive offsets; post-fill: end(n)
__device__ float  g_inv [NN];
__device__ int    g_csr [EE];
__device__ float  g_y1  [NN * HH];
__device__ float  g_z1  [NN * HH];
__device__ float2 g_p   [NN];
__device__ float2 g_q   [NN];
__device__ float  g_s1  [NN];
__device__ float  g_s2  [NN];
__device__ float  g_u   [66];
__device__ float  g_partial[64];
__device__ int    g_ctr [4];        // [0]=scan done, [1]=loss done, [2]=boff ready

// f32x2 packed math (sm_100+)
#define PK(d, lo, hi)  asm("mov.b64 %0, {%1,%2};" : "=l"(d) : "f"(lo), "f"(hi))
#define UPK(lo, hi, s) asm("mov.b64 {%0,%1}, %2;" : "=f"(lo), "=f"(hi) : "l"(s))
#define FMA2(d, a, b)  asm("fma.rn.f32x2 %0, %1, %2, %0;" : "+l"(d) : "l"(a), "l"(b))

// ---------------- K_projdeg: proj GEMM + degree histogram + weight prep ----
__global__ void k_projdeg(const float* __restrict__ x,
                          const float* __restrict__ w1l,
                          const float* __restrict__ w1r,
                          const int*   __restrict__ dst,
                          const float* __restrict__ w2l,
                          const float* __restrict__ w2r,
                          const float* __restrict__ b2,
                          const float* __restrict__ wc) {
    __shared__ float sw[DD * 32];
    __shared__ float sxT[32 * 132];
    const int tid = threadIdx.x;

    if (blockIdx.x >= PROJ_BLOCKS + DEG_BLOCKS) {
        // ---- weight-collapse block (last) ----
        int t = tid;
        if (t < 64) {
            int which = t >> 4, j = t & 15;
            const float* w = (which == 0 || which == 2) ? w2l : w2r;
            const float* c = (which < 2) ? wc : (wc + DD);
            float s = 0.f;
            for (int d = 0; d < DD; d++) s += w[j * DD + d] * c[d];
            g_u[which * 16 + j] = s;
        }
        if (t == 64) { float s = 0.f; for (int d = 0; d < DD; d++) s += b2[d] * wc[d];      g_u[64] = s; }
        if (t == 65) { float s = 0.f; for (int d = 0; d < DD; d++) s += b2[d] * wc[DD + d]; g_u[65] = s; }
        return;
    }

    if (blockIdx.x >= PROJ_BLOCKS) {
        // ---- degree histogram ----
        int idx = (blockIdx.x - PROJ_BLOCKS) * 256 + tid;
        if (idx < EE / 4) {
            int4 d = reinterpret_cast<const int4*>(dst)[idx];
            atomicAdd(&g_degi[d.x], 1);
            atomicAdd(&g_degi[d.y], 1);
            atomicAdd(&g_degi[d.z], 1);
            atomicAdd(&g_degi[d.w], 1);
        }
        return;
    }

    // ---- proj: y1 = x@w1_l, z1 = x@w1_r (f32x2 packed) ----
    for (int i = tid; i < DD * 32; i += 256) {
        int k = i >> 5, j = i & 31;
        sw[i] = (j < 16) ? w1l[k * HH + j] : w1r[k * HH + (j - 16)];
    }

    const int row0 = blockIdx.x * 128;
    const int rq = tid >> 3;
    const int g  = tid & 7;

    u64 accp[2][4];
#pragma unroll
    for (int i = 0; i < 2; i++)
#pragma unroll
        for (int j = 0; j < 4; j++) accp[i][j] = 0ull;

    const int rs = tid >> 3;
    const int q  = tid & 7;

    for (int kc = 0; kc < 4; kc++) {
        __syncthreads();
#pragma unroll
        for (int rr = rs; rr < 128; rr += 32) {
            int row = row0 + rr;
            float4 v = make_float4(0.f, 0.f, 0.f, 0.f);
            if (row < NN)
                v = reinterpret_cast<const float4*>(x + row * DD + kc * 32)[q];
            sxT[(q * 4 + 0) * 132 + rr] = v.x;
            sxT[(q * 4 + 1) * 132 + rr] = v.y;
            sxT[(q * 4 + 2) * 132 + rr] = v.z;
            sxT[(q * 4 + 3) * 132 + rr] = v.w;
        }
        __syncthreads();
#pragma unroll
        for (int kk = 0; kk < 32; kk++) {
            float4 xv = *reinterpret_cast<const float4*>(&sxT[kk * 132 + rq * 4]);
            float4 wv = *reinterpret_cast<const float4*>(&sw[(kc * 32 + kk) * 32 + g * 4]);
            u64 x01, x23, w0, w1, w2, w3;
            PK(x01, xv.x, xv.y);
            PK(x23, xv.z, xv.w);
            PK(w0, wv.x, wv.x);
            PK(w1, wv.y, wv.y);
            PK(w2, wv.z, wv.z);
            PK(w3, wv.w, wv.w);
            FMA2(accp[0][0], x01, w0); FMA2(accp[1][0], x23, w0);
            FMA2(accp[0][1], x01, w1); FMA2(accp[1][1], x23, w1);
            FMA2(accp[0][2], x01, w2); FMA2(accp[1][2], x23, w2);
            FMA2(accp[0][3], x01, w3); FMA2(accp[1][3], x23, w3);
        }
    }

    float acc[4][4];
#pragma unroll
    for (int j = 0; j < 4; j++) {
        UPK(acc[0][j], acc[1][j], accp[0][j]);
        UPK(acc[2][j], acc[3][j], accp[1][j]);
    }

#pragma unroll
    for (int i = 0; i < 4; i++) {
        int row = row0 + rq * 4 + i;
        if (row < NN) {
            float4 v = make_float4(acc[i][0], acc[i][1], acc[i][2], acc[i][3]);
            if (g < 4) reinterpret_cast<float4*>(g_y1 + row * HH)[g]     = v;
            else       reinterpret_cast<float4*>(g_z1 + row * HH)[g - 4] = v;
        }
    }
}

// ---------------- K_scan: single-kernel scan (all 98 blocks resident) ------
// Block scan -> last-arriving block scans block totals -> all blocks finalize.
__global__ void k_scan() {
    __shared__ int ws[32];
    __shared__ int sb[128];
    __shared__ bool s_last;
    __shared__ int s_boff;
    int tid = threadIdx.x, lane = tid & 31, w = tid >> 5;
    int n = blockIdx.x * 1024 + tid;
    int d = (n < NN) ? g_degi[n] : 0;
    int x = d;
#pragma unroll
    for (int o = 1; o < 32; o <<= 1) {
        int t = __shfl_up_sync(FULL, x, o);
        if (lane >= o) x += t;
    }
    if (lane == 31) ws[w] = x;
    __syncthreads();
    if (w == 0) {
        int b = ws[lane];
#pragma unroll
        for (int o = 1; o < 32; o <<= 1) {
            int t = __shfl_up_sync(FULL, b, o);
            if (lane >= o) b += t;
        }
        ws[lane] = b;
    }
    __syncthreads();
    int incl = x + (w > 0 ? ws[w - 1] : 0);

    if (tid == 0) {
        g_bsum[blockIdx.x] = ws[31];
        __threadfence();
        s_last = (atomicAdd(&g_ctr[0], 1) == SCAN_BLOCKS - 1);
    }
    __syncthreads();

    if (s_last) {
        // 128-thread Hillis-Steele scan of the 98 block totals
        int v = 0;
        if (tid < 128) {
            v = (tid < SCAN_BLOCKS) ? atomicAdd(&g_bsum[tid], 0) : 0;
            sb[tid] = v;
        }
        __syncthreads();
        for (int o = 1; o < 128; o <<= 1) {
            int t = (tid >= o && tid < 128) ? sb[tid - o] : 0;
            __syncthreads();
            if (tid < 128) sb[tid] += t;
            __syncthreads();
        }
        if (tid < SCAN_BLOCKS) g_boff[tid] = sb[tid] - v;   // exclusive
        __threadfence();
        if (tid == 0) atomicExch(&g_ctr[2], 1);
    } else if (tid == 0) {
        while (atomicAdd(&g_ctr[2], 0) == 0) {}
    }
    __syncthreads();
    if (tid == 0) s_boff = atomicAdd(&g_boff[blockIdx.x], 0);
    __syncthreads();

    if (n < NN) {
        g_row[n] = s_boff + incl - d;       // exclusive offset (cursor)
        g_inv[n] = 1.f / (float)max(d, 1);
    }
}

// ---------------- K_fill: scatter edges into CSR (bumps g_row) -------------
__global__ void k_fill(const int* __restrict__ src, const int* __restrict__ dst) {
    int idx = blockIdx.x * blockDim.x + threadIdx.x;
    if (idx >= EE / 4) return;
    int4 s = reinterpret_cast<const int4*>(src)[idx];
    int4 d = reinterpret_cast<const int4*>(dst)[idx];
    int p0 = atomicAdd(&g_row[d.x], 1); g_csr[p0] = s.x;
    int p1 = atomicAdd(&g_row[d.y], 1); g_csr[p1] = s.y;
    int p2 = atomicAdd(&g_row[d.z], 1); g_csr[p2] = s.z;
    int p3 = atomicAdd(&g_row[d.w], 1); g_csr[p3] = s.w;
}

// ---------------- K_gagg1: quad-gather y1 (MLP-8) + fused h + contraction --
__global__ void k_gagg1(const float* __restrict__ b1) {
    __shared__ float su[64];
    __shared__ float sb[16];
    int tid = threadIdx.x;
    if (tid < 64) su[tid] = g_u[tid];
    if (tid < 16) sb[tid] = b1[tid];
    __syncthreads();

    int t = blockIdx.x * 256 + tid;
    int n = t >> 2, c = t & 3;
    bool valid = (n < NN);
    int ncl = valid ? n : (NN - 1);

    const unsigned qmask = 0xFu << (threadIdx.x & 28);

    int deg = g_degi[ncl];
    int end = g_row[ncl];
    int beg = end - deg;
    float4 acc = make_float4(0.f, 0.f, 0.f, 0.f);
    int last = end - 1;
    for (int j = beg; j < end; j += 8) {
        int ja = min(j + c, last), jb = min(j + 4 + c, last);
        int ia = g_csr[ja], ib = g_csr[jb];
        int s0 = __shfl_sync(qmask, ia, 0, 4);
        int s1 = __shfl_sync(qmask, ia, 1, 4);
        int s2 = __shfl_sync(qmask, ia, 2, 4);
        int s3 = __shfl_sync(qmask, ia, 3, 4);
        int s4 = __shfl_sync(qmask, ib, 0, 4);
        int s5 = __shfl_sync(qmask, ib, 1, 4);
        int s6 = __shfl_sync(qmask, ib, 2, 4);
        int s7 = __shfl_sync(qmask, ib, 3, 4);
        float w1 = (j + 1 < end) ? 1.f : 0.f;
        float w2 = (j + 2 < end) ? 1.f : 0.f;
        float w3 = (j + 3 < end) ? 1.f : 0.f;
        float w4 = (j + 4 < end) ? 1.f : 0.f;
        float w5 = (j + 5 < end) ? 1.f : 0.f;
        float w6 = (j + 6 < end) ? 1.f : 0.f;
        float w7 = (j + 7 < end) ? 1.f : 0.f;
        float4 v0 = reinterpret_cast<const float4*>(g_y1 + (size_t)s0 * HH)[c];
        float4 v1 = reinterpret_cast<const float4*>(g_y1 + (size_t)s1 * HH)[c];
        float4 v2 = reinterpret_cast<const float4*>(g_y1 + (size_t)s2 * HH)[c];
        float4 v3 = reinterpret_cast<const float4*>(g_y1 + (size_t)s3 * HH)[c];
        float4 v4 = reinterpret_cast<const float4*>(g_y1 + (size_t)s4 * HH)[c];
        float4 v5 = reinterpret_cast<const float4*>(g_y1 + (size_t)s5 * HH)[c];
        float4 v6 = reinterpret_cast<const float4*>(g_y1 + (size_t)s6 * HH)[c];
        float4 v7 = reinterpret_cast<const float4*>(g_y1 + (size_t)s7 * HH)[c];
        acc.x += v0.x + fmaf(w1, v1.x, fmaf(w2, v2.x, w3 * v3.x))
                      + fmaf(w4, v4.x, fmaf(w5, v5.x, fmaf(w6, v6.x, w7 * v7.x)));
        acc.y += v0.y + fmaf(w1, v1.y, fmaf(w2, v2.y, w3 * v3.y))
                      + fmaf(w4, v4.y, fmaf(w5, v5.y, fmaf(w6, v6.y, w7 * v7.y)));
        acc.z += v0.z + fmaf(w1, v1.z, fmaf(w2, v2.z, w3 * v3.z))
                      + fmaf(w4, v4.z, fmaf(w5, v5.z, fmaf(w6, v6.z, w7 * v7.z)));
        acc.w += v0.w + fmaf(w1, v1.w, fmaf(w2, v2.w, w3 * v3.w))
                      + fmaf(w4, v4.w, fmaf(w5, v5.w, fmaf(w6, v6.w, w7 * v7.w)));
    }

    float inv = g_inv[ncl];
    float4 z = reinterpret_cast<const float4*>(g_z1 + (size_t)ncl * HH)[c];
    int j0 = c * 4;
    float h0 = fmaxf(acc.x * inv + sb[j0 + 0] + z.x, 0.f);
    float h1 = fmaxf(acc.y * inv + sb[j0 + 1] + z.y, 0.f);
    float h2 = fmaxf(acc.z * inv + sb[j0 + 2] + z.z, 0.f);
    float h3 = fmaxf(acc.w * inv + sb[j0 + 3] + z.w, 0.f);

    float p1 = h0 * su[j0]      + h1 * su[j0 + 1]  + h2 * su[j0 + 2]  + h3 * su[j0 + 3];
    float q1 = h0 * su[16 + j0] + h1 * su[17 + j0] + h2 * su[18 + j0] + h3 * su[19 + j0];
    float p2 = h0 * su[32 + j0] + h1 * su[33 + j0] + h2 * su[34 + j0] + h3 * su[35 + j0];
    float q2 = h0 * su[48 + j0] + h1 * su[49 + j0] + h2 * su[50 + j0] + h3 * su[51 + j0];

    p1 += __shfl_xor_sync(FULL, p1, 1); p1 += __shfl_xor_sync(FULL, p1, 2);
    p2 += __shfl_xor_sync(FULL, p2, 1); p2 += __shfl_xor_sync(FULL, p2, 2);
    q1 += __shfl_xor_sync(FULL, q1, 1); q1 += __shfl_xor_sync(FULL, q1, 2);
    q2 += __shfl_xor_sync(FULL, q2, 1); q2 += __shfl_xor_sync(FULL, q2, 2);

    if (valid && c == 0) {
        g_p[n] = make_float2(p1, p2);
        g_q[n] = make_float2(q1, q2);
    }
}

// ---------------- K_gagg2: gather-aggregate p (MLP-8) + classifier scalars -
__global__ void k_gagg2() {
    int n = blockIdx.x * blockDim.x + threadIdx.x;
    if (n >= NN) return;
    int deg = g_degi[n];
    int end = g_row[n];
    int beg = end - deg;
    float ax = 0.f, ay = 0.f;
    int last = end - 1;
    for (int j = beg; j < end; j += 8) {
        int j1 = min(j + 1, last), j2 = min(j + 2, last), j3 = min(j + 3, last);
        int j4 = min(j + 4, last), j5 = min(j + 5, last), j6 = min(j + 6, last), j7 = min(j + 7, last);
        int s0 = g_csr[j],  s1 = g_csr[j1], s2 = g_csr[j2], s3 = g_csr[j3];
        int s4 = g_csr[j4], s5 = g_csr[j5], s6 = g_csr[j6], s7 = g_csr[j7];
        float w1 = (j + 1 < end) ? 1.f : 0.f;
        float w2 = (j + 2 < end) ? 1.f : 0.f;
        float w3 = (j + 3 < end) ? 1.f : 0.f;
        float w4 = (j + 4 < end) ? 1.f : 0.f;
        float w5 = (j + 5 < end) ? 1.f : 0.f;
        float w6 = (j + 6 < end) ? 1.f : 0.f;
        float w7 = (j + 7 < end) ? 1.f : 0.f;
        float2 v0 = g_p[s0], v1 = g_p[s1], v2 = g_p[s2], v3 = g_p[s3];
        float2 v4 = g_p[s4], v5 = g_p[s5], v6 = g_p[s6], v7 = g_p[s7];
        ax += v0.x + fmaf(w1, v1.x, fmaf(w2, v2.x, w3 * v3.x))
                   + fmaf(w4, v4.x, fmaf(w5, v5.x, fmaf(w6, v6.x, w7 * v7.x)));
        ay += v0.y + fmaf(w1, v1.y, fmaf(w2, v2.y, w3 * v3.y))
                   + fmaf(w4, v4.y, fmaf(w5, v5.y, fmaf(w6, v6.y, w7 * v7.y)));
    }
    float inv = g_inv[n];
    float2 q = g_q[n];
    g_s1[n] = ax * inv + q.x + g_u[64];
    g_s2[n] = ay * inv + q.y + g_u[65];
}

// ---------------- K_loss: logits + BCE, fused final reduce ------------------
__global__ void k_loss(const int* __restrict__ a1, const int* __restrict__ a2,
                       const int* __restrict__ labels, const float* __restrict__ bc,
                       float* __restrict__ out) {
    int tid = threadIdx.x;
    float bias = bc[0];
    int i = blockIdx.x * 256 + tid;   // 64*256 == BB exactly
    float l = g_s1[a1[i]] + g_s2[a2[i]] + bias;
    out[1 + i] = l;
    float y = (float)labels[i];
    float acc = fmaxf(l, 0.f) - l * y + log1pf(expf(-fabsf(l)));

    __shared__ float sred[256];
    __shared__ bool s_last;
    sred[tid] = acc;
    __syncthreads();
    for (int s = 128; s > 0; s >>= 1) {
        if (tid < s) sred[tid] += sred[tid + s];
        __syncthreads();
    }
    if (tid == 0) {
        g_partial[blockIdx.x] = sred[0];
        __threadfence();
        s_last = (atomicAdd(&g_ctr[1], 1) == 63);
    }
    __syncthreads();
    if (s_last) {
        float v = (tid < 64) ? g_partial[tid] : 0.f;
        sred[tid] = v;
        __syncthreads();
        for (int s = 32; s > 0; s >>= 1) {
            if (tid < s) sred[tid] += sred[tid + s];
            __syncthreads();
        }
        if (tid == 0) out[0] = sred[0] * (1.f / (float)BB);
    }
}

// ---------------- launch ----------------------------------------------------
extern "C" void kernel_launch(void* const* d_in, const int* in_sizes, int n_in,
                              void* d_out, int out_size) {
    const float* x    = (const float*)d_in[0];
    const float* w1l  = (const float*)d_in[1];
    const float* b1   = (const float*)d_in[2];
    const float* w1r  = (const float*)d_in[3];
    const float* w2l  = (const float*)d_in[4];
    const float* b2   = (const float*)d_in[5];
    const float* w2r  = (const float*)d_in[6];
    const float* wc   = (const float*)d_in[7];
    const float* bc   = (const float*)d_in[8];
    const int*   edge = (const int*)d_in[9];
    const int*   a1   = (const int*)d_in[10];
    const int*   a2   = (const int*)d_in[11];
    const int*   lab  = (const int*)d_in[12];
    float* out = (float*)d_out;

    const int* src = edge;
    const int* dst = edge + EE;

    void *p_degi = nullptr, *p_ctr = nullptr;
    cudaGetSymbolAddress(&p_degi, g_degi);
    cudaGetSymbolAddress(&p_ctr,  g_ctr);
    cudaMemsetAsync(p_degi, 0, NN * sizeof(int));
    cudaMemsetAsync(p_ctr,  0, 4 * sizeof(int));

    k_projdeg<<<PROJ_BLOCKS + DEG_BLOCKS + 1, 256>>>(x, w1l, w1r, dst, w2l, w2r, b2, wc);
    k_scan   <<<SCAN_BLOCKS, 1024>>>();
    k_fill   <<<(EE / 4 + 255) / 256, 256>>>(src, dst);
    k_gagg1  <<<(NN * 4 + 255) / 256, 256>>>(b1);
    k_gagg2  <<<(NN + 255) / 256, 256>>>();
    k_loss   <<<64, 256>>>(a1, a2, lab, bc, out);
}

// round 10
// speedup vs baseline: 1.0478x; 1.0478x over previous
#include <cuda_runtime.h>
#include <cuda_fp16.h>
#include <math.h>

#define NN 100000
#define DD 128
#define HH 16
#define EE 1600000
#define BB 16384
#define FULL 0xffffffffu

#define PROJ_BLOCKS ((NN + 127) / 128)      // 782
#define DEG_BLOCKS  ((EE / 4 + 255) / 256)  // 1563
#define SCAN_BLOCKS 98
#define G2_BLOCKS   ((NN + 255) / 256)      // 391

typedef unsigned long long u64;

// ---------------- scratch (device globals) ---------------------------------
__device__ int    g_degi[NN];
__device__ int    g_bsum[SCAN_BLOCKS];
__device__ int    g_boff[SCAN_BLOCKS];
__device__ int    g_row [NN];       // exclusive offsets; post-fill: end(n)
__device__ float  g_inv [NN];
__device__ int    g_csr [EE];
__device__ __half g_y1h [NN * HH];  // x @ w1_l, fp16 (gather payload)
__device__ float  g_z1  [NN * HH];  // x @ w1_r, fp32 (sequential)
__device__ float2 g_p   [NN];
__device__ float2 g_q   [NN];
__device__ float  g_s1  [NN];
__device__ float  g_s2  [NN];
__device__ float  g_u   [66];
__device__ float  g_partial[64];
__device__ int    g_ctr [4];        // [0]=scan done, [2]=boff ready, [3]=gagg2 done

// f32x2 packed math (sm_100+)
#define PK(d, lo, hi)  asm("mov.b64 %0, {%1,%2};" : "=l"(d) : "f"(lo), "f"(hi))
#define UPK(lo, hi, s) asm("mov.b64 {%0,%1}, %2;" : "=f"(lo), "=f"(hi) : "l"(s))
#define FMA2(d, a, b)  asm("fma.rn.f32x2 %0, %1, %2, %0;" : "+l"(d) : "l"(a), "l"(b))

// load 4 halves (dims c*4..c*4+3 of node s) and widen to float4
__device__ __forceinline__ float4 ldh4(int s, int c) {
    uint2 r = *reinterpret_cast<const uint2*>(g_y1h + (size_t)s * HH + c * 4);
    __half2 h0 = *reinterpret_cast<__half2*>(&r.x);
    __half2 h1 = *reinterpret_cast<__half2*>(&r.y);
    float2 f0 = __half22float2(h0), f1 = __half22float2(h1);
    return make_float4(f0.x, f0.y, f1.x, f1.y);
}

// ---------------- K_projdeg: proj GEMM + degree histogram + weight prep ----
__global__ void k_projdeg(const float* __restrict__ x,
                          const float* __restrict__ w1l,
                          const float* __restrict__ w1r,
                          const int*   __restrict__ dst,
                          const float* __restrict__ w2l,
                          const float* __restrict__ w2r,
                          const float* __restrict__ b2,
                          const float* __restrict__ wc) {
    __shared__ float sw[DD * 32];
    __shared__ float sxT[32 * 132];
    const int tid = threadIdx.x;

    if (blockIdx.x >= PROJ_BLOCKS + DEG_BLOCKS) {
        // ---- weight-collapse block (last) ----
        int t = tid;
        if (t < 64) {
            int which = t >> 4, j = t & 15;
            const float* w = (which == 0 || which == 2) ? w2l : w2r;
            const float* c = (which < 2) ? wc : (wc + DD);
            float s = 0.f;
            for (int d = 0; d < DD; d++) s += w[j * DD + d] * c[d];
            g_u[which * 16 + j] = s;
        }
        if (t == 64) { float s = 0.f; for (int d = 0; d < DD; d++) s += b2[d] * wc[d];      g_u[64] = s; }
        if (t == 65) { float s = 0.f; for (int d = 0; d < DD; d++) s += b2[d] * wc[DD + d]; g_u[65] = s; }
        return;
    }

    if (blockIdx.x >= PROJ_BLOCKS) {
        // ---- degree histogram ----
        int idx = (blockIdx.x - PROJ_BLOCKS) * 256 + tid;
        if (idx < EE / 4) {
            int4 d = reinterpret_cast<const int4*>(dst)[idx];
            atomicAdd(&g_degi[d.x], 1);
            atomicAdd(&g_degi[d.y], 1);
            atomicAdd(&g_degi[d.z], 1);
            atomicAdd(&g_degi[d.w], 1);
        }
        return;
    }

    // ---- proj: y1 = x@w1_l (->fp16), z1 = x@w1_r (f32x2 packed) ----
    for (int i = tid; i < DD * 32; i += 256) {
        int k = i >> 5, j = i & 31;
        sw[i] = (j < 16) ? w1l[k * HH + j] : w1r[k * HH + (j - 16)];
    }

    const int row0 = blockIdx.x * 128;
    const int rq = tid >> 3;
    const int g  = tid & 7;

    u64 accp[2][4];
#pragma unroll
    for (int i = 0; i < 2; i++)
#pragma unroll
        for (int j = 0; j < 4; j++) accp[i][j] = 0ull;

    const int rs = tid >> 3;
    const int q  = tid & 7;

    for (int kc = 0; kc < 4; kc++) {
        __syncthreads();
#pragma unroll
        for (int rr = rs; rr < 128; rr += 32) {
            int row = row0 + rr;
            float4 v = make_float4(0.f, 0.f, 0.f, 0.f);
            if (row < NN)
                v = reinterpret_cast<const float4*>(x + row * DD + kc * 32)[q];
            sxT[(q * 4 + 0) * 132 + rr] = v.x;
            sxT[(q * 4 + 1) * 132 + rr] = v.y;
            sxT[(q * 4 + 2) * 132 + rr] = v.z;
            sxT[(q * 4 + 3) * 132 + rr] = v.w;
        }
        __syncthreads();
#pragma unroll
        for (int kk = 0; kk < 32; kk++) {
            float4 xv = *reinterpret_cast<const float4*>(&sxT[kk * 132 + rq * 4]);
            float4 wv = *reinterpret_cast<const float4*>(&sw[(kc * 32 + kk) * 32 + g * 4]);
            u64 x01, x23, w0, w1, w2, w3;
            PK(x01, xv.x, xv.y);
            PK(x23, xv.z, xv.w);
            PK(w0, wv.x, wv.x);
            PK(w1, wv.y, wv.y);
            PK(w2, wv.z, wv.z);
            PK(w3, wv.w, wv.w);
            FMA2(accp[0][0], x01, w0); FMA2(accp[1][0], x23, w0);
            FMA2(accp[0][1], x01, w1); FMA2(accp[1][1], x23, w1);
            FMA2(accp[0][2], x01, w2); FMA2(accp[1][2], x23, w2);
            FMA2(accp[0][3], x01, w3); FMA2(accp[1][3], x23, w3);
        }
    }

    float acc[4][4];
#pragma unroll
    for (int j = 0; j < 4; j++) {
        UPK(acc[0][j], acc[1][j], accp[0][j]);
        UPK(acc[2][j], acc[3][j], accp[1][j]);
    }

#pragma unroll
    for (int i = 0; i < 4; i++) {
        int row = row0 + rq * 4 + i;
        if (row < NN) {
            if (g < 4) {
                // y1 -> fp16 packed (4 halves = 8B)
                __half2 ha = __floats2half2_rn(acc[i][0], acc[i][1]);
                __half2 hb = __floats2half2_rn(acc[i][2], acc[i][3]);
                uint2 pk;
                *reinterpret_cast<__half2*>(&pk.x) = ha;
                *reinterpret_cast<__half2*>(&pk.y) = hb;
                *reinterpret_cast<uint2*>(g_y1h + (size_t)row * HH + g * 4) = pk;
            } else {
                float4 v = make_float4(acc[i][0], acc[i][1], acc[i][2], acc[i][3]);
                reinterpret_cast<float4*>(g_z1 + (size_t)row * HH)[g - 4] = v;
            }
        }
    }
}

// ---------------- K_scan: single-kernel scan (all 98 blocks resident) ------
__global__ void k_scan() {
    __shared__ int ws[32];
    __shared__ int sb[128];
    __shared__ bool s_last;
    __shared__ int s_boff;
    int tid = threadIdx.x, lane = tid & 31, w = tid >> 5;
    int n = blockIdx.x * 1024 + tid;
    int d = (n < NN) ? g_degi[n] : 0;
    int x = d;
#pragma unroll
    for (int o = 1; o < 32; o <<= 1) {
        int t = __shfl_up_sync(FULL, x, o);
        if (lane >= o) x += t;
    }
    if (lane == 31) ws[w] = x;
    __syncthreads();
    if (w == 0) {
        int b = ws[lane];
#pragma unroll
        for (int o = 1; o < 32; o <<= 1) {
            int t = __shfl_up_sync(FULL, b, o);
            if (lane >= o) b += t;
        }
        ws[lane] = b;
    }
    __syncthreads();
    int incl = x + (w > 0 ? ws[w - 1] : 0);

    if (tid == 0) {
        g_bsum[blockIdx.x] = ws[31];
        __threadfence();
        s_last = (atomicAdd(&g_ctr[0], 1) == SCAN_BLOCKS - 1);
    }
    __syncthreads();

    if (s_last) {
        int v = 0;
        if (tid < 128) {
            v = (tid < SCAN_BLOCKS) ? atomicAdd(&g_bsum[tid], 0) : 0;
            sb[tid] = v;
        }
        __syncthreads();
        for (int o = 1; o < 128; o <<= 1) {
            int t = (tid >= o && tid < 128) ? sb[tid - o] : 0;
            __syncthreads();
            if (tid < 128) sb[tid] += t;
            __syncthreads();
        }
        if (tid < SCAN_BLOCKS) g_boff[tid] = sb[tid] - v;   // exclusive
        __threadfence();
        if (tid == 0) atomicExch(&g_ctr[2], 1);
    } else if (tid == 0) {
        while (atomicAdd(&g_ctr[2], 0) == 0) __nanosleep(64);
    }
    __syncthreads();
    if (tid == 0) s_boff = atomicAdd(&g_boff[blockIdx.x], 0);
    __syncthreads();

    if (n < NN) {
        g_row[n] = s_boff + incl - d;       // exclusive offset (cursor)
        g_inv[n] = 1.f / (float)max(d, 1);
    }
}

// ---------------- K_fill: scatter edges into CSR (bumps g_row) -------------
__global__ void k_fill(const int* __restrict__ src, const int* __restrict__ dst) {
    int idx = blockIdx.x * blockDim.x + threadIdx.x;
    if (idx >= EE / 4) return;
    int4 s = reinterpret_cast<const int4*>(src)[idx];
    int4 d = reinterpret_cast<const int4*>(dst)[idx];
    int p0 = atomicAdd(&g_row[d.x], 1); g_csr[p0] = s.x;
    int p1 = atomicAdd(&g_row[d.y], 1); g_csr[p1] = s.y;
    int p2 = atomicAdd(&g_row[d.z], 1); g_csr[p2] = s.z;
    int p3 = atomicAdd(&g_row[d.w], 1); g_csr[p3] = s.w;
}

// ---------------- K_gagg1: quad-gather y1 fp16 (MLP-8) + fused h + contract
__global__ void k_gagg1(const float* __restrict__ b1) {
    __shared__ float su[64];
    __shared__ float sb[16];
    int tid = threadIdx.x;
    if (tid < 64) su[tid] = g_u[tid];
    if (tid < 16) sb[tid] = b1[tid];
    __syncthreads();

    int t = blockIdx.x * 256 + tid;
    int n = t >> 2, c = t & 3;
    bool valid = (n < NN);
    int ncl = valid ? n : (NN - 1);

    const unsigned qmask = 0xFu << (threadIdx.x & 28);

    int deg = g_degi[ncl];
    int end = g_row[ncl];
    int beg = end - deg;
    float4 acc = make_float4(0.f, 0.f, 0.f, 0.f);
    int last = end - 1;
    for (int j = beg; j < end; j += 8) {
        int ja = min(j + c, last), jb = min(j + 4 + c, last);
        int ia = g_csr[ja], ib = g_csr[jb];
        int s0 = __shfl_sync(qmask, ia, 0, 4);
        int s1 = __shfl_sync(qmask, ia, 1, 4);
        int s2 = __shfl_sync(qmask, ia, 2, 4);
        int s3 = __shfl_sync(qmask, ia, 3, 4);
        int s4 = __shfl_sync(qmask, ib, 0, 4);
        int s5 = __shfl_sync(qmask, ib, 1, 4);
        int s6 = __shfl_sync(qmask, ib, 2, 4);
        int s7 = __shfl_sync(qmask, ib, 3, 4);
        float w1 = (j + 1 < end) ? 1.f : 0.f;
        float w2 = (j + 2 < end) ? 1.f : 0.f;
        float w3 = (j + 3 < end) ? 1.f : 0.f;
        float w4 = (j + 4 < end) ? 1.f : 0.f;
        float w5 = (j + 5 < end) ? 1.f : 0.f;
        float w6 = (j + 6 < end) ? 1.f : 0.f;
        float w7 = (j + 7 < end) ? 1.f : 0.f;
        float4 v0 = ldh4(s0, c);
        float4 v1 = ldh4(s1, c);
        float4 v2 = ldh4(s2, c);
        float4 v3 = ldh4(s3, c);
        float4 v4 = ldh4(s4, c);
        float4 v5 = ldh4(s5, c);
        float4 v6 = ldh4(s6, c);
        float4 v7 = ldh4(s7, c);
        acc.x += v0.x + fmaf(w1, v1.x, fmaf(w2, v2.x, w3 * v3.x))
                      + fmaf(w4, v4.x, fmaf(w5, v5.x, fmaf(w6, v6.x, w7 * v7.x)));
        acc.y += v0.y + fmaf(w1, v1.y, fmaf(w2, v2.y, w3 * v3.y))
                      + fmaf(w4, v4.y, fmaf(w5, v5.y, fmaf(w6, v6.y, w7 * v7.y)));
        acc.z += v0.z + fmaf(w1, v1.z, fmaf(w2, v2.z, w3 * v3.z))
                      + fmaf(w4, v4.z, fmaf(w5, v5.z, fmaf(w6, v6.z, w7 * v7.z)));
        acc.w += v0.w + fmaf(w1, v1.w, fmaf(w2, v2.w, w3 * v3.w))
                      + fmaf(w4, v4.w, fmaf(w5, v5.w, fmaf(w6, v6.w, w7 * v7.w)));
    }

    float inv = g_inv[ncl];
    float4 z = reinterpret_cast<const float4*>(g_z1 + (size_t)ncl * HH)[c];
    int j0 = c * 4;
    float h0 = fmaxf(acc.x * inv + sb[j0 + 0] + z.x, 0.f);
    float h1 = fmaxf(acc.y * inv + sb[j0 + 1] + z.y, 0.f);
    float h2 = fmaxf(acc.z * inv + sb[j0 + 2] + z.z, 0.f);
    float h3 = fmaxf(acc.w * inv + sb[j0 + 3] + z.w, 0.f);

    float p1 = h0 * su[j0]      + h1 * su[j0 + 1]  + h2 * su[j0 + 2]  + h3 * su[j0 + 3];
    float q1 = h0 * su[16 + j0] + h1 * su[17 + j0] + h2 * su[18 + j0] + h3 * su[19 + j0];
    float p2 = h0 * su[32 + j0] + h1 * su[33 + j0] + h2 * su[34 + j0] + h3 * su[35 + j0];
    float q2 = h0 * su[48 + j0] + h1 * su[49 + j0] + h2 * su[50 + j0] + h3 * su[51 + j0];

    p1 += __shfl_xor_sync(FULL, p1, 1); p1 += __shfl_xor_sync(FULL, p1, 2);
    p2 += __shfl_xor_sync(FULL, p2, 1); p2 += __shfl_xor_sync(FULL, p2, 2);
    q1 += __shfl_xor_sync(FULL, q1, 1); q1 += __shfl_xor_sync(FULL, q1, 2);
    q2 += __shfl_xor_sync(FULL, q2, 1); q2 += __shfl_xor_sync(FULL, q2, 2);

    if (valid && c == 0) {
        g_p[n] = make_float2(p1, p2);
        g_q[n] = make_float2(q1, q2);
    }
}

// ---------------- K_gagg2loss: p-aggregation + classifier, then loss -------
// Blocks [0, G2_BLOCKS): per-node scalars. Blocks [G2_BLOCKS, +64): spin until
// all scalar blocks done (all 455 blocks resident in wave 1), then loss.
__global__ void k_gagg2loss(const int* __restrict__ a1, const int* __restrict__ a2,
                            const int* __restrict__ labels, const float* __restrict__ bc,
                            float* __restrict__ out) {
    int tid = threadIdx.x;
    __shared__ float sred[256];
    __shared__ bool s_last;

    if (blockIdx.x < G2_BLOCKS) {
        int n = blockIdx.x * 256 + tid;
        if (n < NN) {
            int deg = g_degi[n];
            int end = g_row[n];
            int beg = end - deg;
            float ax = 0.f, ay = 0.f;
            int last = end - 1;
            for (int j = beg; j < end; j += 8) {
                int j1 = min(j + 1, last), j2 = min(j + 2, last), j3 = min(j + 3, last);
                int j4 = min(j + 4, last), j5 = min(j + 5, last), j6 = min(j + 6, last), j7 = min(j + 7, last);
                int s0 = g_csr[j],  s1 = g_csr[j1], s2 = g_csr[j2], s3 = g_csr[j3];
                int s4 = g_csr[j4], s5 = g_csr[j5], s6 = g_csr[j6], s7 = g_csr[j7];
                float w1 = (j + 1 < end) ? 1.f : 0.f;
                float w2 = (j + 2 < end) ? 1.f : 0.f;
                float w3 = (j + 3 < end) ? 1.f : 0.f;
                float w4 = (j + 4 < end) ? 1.f : 0.f;
                float w5 = (j + 5 < end) ? 1.f : 0.f;
                float w6 = (j + 6 < end) ? 1.f : 0.f;
                float w7 = (j + 7 < end) ? 1.f : 0.f;
                float2 v0 = g_p[s0], v1 = g_p[s1], v2 = g_p[s2], v3 = g_p[s3];
                float2 v4 = g_p[s4], v5 = g_p[s5], v6 = g_p[s6], v7 = g_p[s7];
                ax += v0.x + fmaf(w1, v1.x, fmaf(w2, v2.x, w3 * v3.x))
                           + fmaf(w4, v4.x, fmaf(w5, v5.x, fmaf(w6, v6.x, w7 * v7.x)));
                ay += v0.y + fmaf(w1, v1.y, fmaf(w2, v2.y, w3 * v3.y))
                           + fmaf(w4, v4.y, fmaf(w5, v5.y, fmaf(w6, v6.y, w7 * v7.y)));
            }
            float inv = g_inv[n];
            float2 q = g_q[n];
            g_s1[n] = ax * inv + q.x + g_u[64];
            g_s2[n] = ay * inv + q.y + g_u[65];
        }
        __syncthreads();
        if (tid == 0) {
            __threadfence();
            atomicAdd(&g_ctr[3], 1);
        }
        return;
    }

    // ---- loss blocks: wait for all scalar blocks ----
    if (tid == 0) {
        while (atomicAdd(&g_ctr[3], 0) < G2_BLOCKS) __nanosleep(128);
    }
    __syncthreads();
    __threadfence();

    int lb = blockIdx.x - G2_BLOCKS;     // 0..63
    float bias = bc[0];
    int i = lb * 256 + tid;              // 64*256 == BB exactly
    float l = g_s1[a1[i]] + g_s2[a2[i]] + bias;
    out[1 + i] = l;
    float y = (float)labels[i];
    float acc = fmaxf(l, 0.f) - l * y + log1pf(expf(-fabsf(l)));

    sred[tid] = acc;
    __syncthreads();
    for (int s = 128; s > 0; s >>= 1) {
        if (tid < s) sred[tid] += sred[tid + s];
        __syncthreads();
    }
    if (tid == 0) {
        g_partial[lb] = sred[0];
        __threadfence();
        s_last = (atomicAdd(&g_ctr[1], 1) == 63);
    }
    __syncthreads();
    if (s_last) {
        float v = (tid < 64) ? g_partial[tid] : 0.f;
        sred[tid] = v;
        __syncthreads();
        for (int s = 32; s > 0; s >>= 1) {
            if (tid < s) sred[tid] += sred[tid + s];
            __syncthreads();
        }
        if (tid == 0) out[0] = sred[0] * (1.f / (float)BB);
    }
}

// ---------------- launch ----------------------------------------------------
extern "C" void kernel_launch(void* const* d_in, const int* in_sizes, int n_in,
                              void* d_out, int out_size) {
    const float* x    = (const float*)d_in[0];
    const float* w1l  = (const float*)d_in[1];
    const float* b1   = (const float*)d_in[2];
    const float* w1r  = (const float*)d_in[3];
    const float* w2l  = (const float*)d_in[4];
    const float* b2   = (const float*)d_in[5];
    const float* w2r  = (const float*)d_in[6];
    const float* wc   = (const float*)d_in[7];
    const float* bc   = (const float*)d_in[8];
    const int*   edge = (const int*)d_in[9];
    const int*   a1   = (const int*)d_in[10];
    const int*   a2   = (const int*)d_in[11];
    const int*   lab  = (const int*)d_in[12];
    float* out = (float*)d_out;

    const int* src = edge;
    const int* dst = edge + EE;

    void *p_degi = nullptr, *p_ctr = nullptr;
    cudaGetSymbolAddress(&p_degi, g_degi);
    cudaGetSymbolAddress(&p_ctr,  g_ctr);
    cudaMemsetAsync(p_degi, 0, NN * sizeof(int));
    cudaMemsetAsync(p_ctr,  0, 4 * sizeof(int));

    k_projdeg  <<<PROJ_BLOCKS + DEG_BLOCKS + 1, 256>>>(x, w1l, w1r, dst, w2l, w2r, b2, wc);
    k_scan     <<<SCAN_BLOCKS, 1024>>>();
    k_fill     <<<(EE / 4 + 255) / 256, 256>>>(src, dst);
    k_gagg1    <<<(NN * 4 + 255) / 256, 256>>>(b1);
    k_gagg2loss<<<G2_BLOCKS + 64, 256>>>(a1, a2, lab, bc, out);
}